// round 12
// baseline (speedup 1.0000x reference)
#include <cuda_runtime.h>
#include <cuda_bf16.h>
#include <math.h>
#include <stdint.h>

// Problem constants
#define Vv 50257
#define Vp 50304            // Vv padded to multiple of 128
#define Dd 384
#define Hh 6
#define HSs 64
#define Ll 6
#define Tt 256
#define Bb 8
#define BT (Bb*Tt)          // 2048 rows
#define QKVN (3*Hh*HSs)     // 1152
#define FF (4*Dd)           // 1536

// -------- device scratch (no allocation allowed) --------
__device__ float g_x   [BT*Dd];
__device__ float g_xn  [BT*Dd];
__device__ float g_qkv [BT*QKVN];
__device__ float g_att [BT*Dd];
__device__ float g_h1  [BT*FF];
__device__ float g_wpk [Ll*Dd*QKVN];   // rounded packed qkv weights
__device__ float g_wpr [Ll*Dd*Dd];     // rounded Wp
__device__ float g_w1r [Ll*Dd*FF];     // rounded W1
__device__ float g_w2r [Ll*FF*Dd];     // rounded W2
__device__ float g_lmp [Dd*Vp];        // rounded+padded lmW

// ============================================================
// helpers
// ============================================================
__device__ __forceinline__ void cp_async16(void* dst, const void* src) {
    uint32_t s = (uint32_t)__cvta_generic_to_shared(dst);
    asm volatile("cp.async.cg.shared.global [%0], [%1], 16;\n" :: "r"(s), "l"(src));
}
#define CP_COMMIT() asm volatile("cp.async.commit_group;\n" ::: "memory")
#define CP_WAIT1()  asm volatile("cp.async.wait_group 1;\n" ::: "memory")
#define CP_WAIT0()  asm volatile("cp.async.wait_group 0;\n" ::: "memory")

__device__ __forceinline__ float tf32r(float x) {
    uint32_t u;
    asm("cvt.rna.tf32.f32 %0, %1;" : "=r"(u) : "f"(x));
    return __uint_as_float(u);
}

__device__ __forceinline__ void mma_tf32(float* c, const uint32_t* a,
                                         uint32_t b0, uint32_t b1) {
    asm volatile(
        "mma.sync.aligned.m16n8k8.row.col.f32.tf32.tf32.f32 "
        "{%0,%1,%2,%3}, {%4,%5,%6,%7}, {%8,%9}, {%0,%1,%2,%3};\n"
        : "+f"(c[0]), "+f"(c[1]), "+f"(c[2]), "+f"(c[3])
        : "r"(a[0]), "r"(a[1]), "r"(a[2]), "r"(a[3]), "r"(b0), "r"(b1));
}

// ============================================================
// Weight rounding / padding (runs every call; deterministic)
// ============================================================
__global__ void round_kernel(const float4* __restrict__ s, float4* __restrict__ d, int n4) {
    int i = blockIdx.x * blockDim.x + threadIdx.x;
    if (i < n4) {
        float4 v = s[i];
        v.x = tf32r(v.x); v.y = tf32r(v.y);
        v.z = tf32r(v.z); v.w = tf32r(v.w);
        d[i] = v;
    }
}
__global__ void lmpad_kernel(const float* __restrict__ lmW, float* __restrict__ dst) {
    int n4 = (blockIdx.x * 256 + threadIdx.x) * 4;   // grid.x = ceil(Vp/1024)
    int k = blockIdx.y;                              // 0..Dd-1
    if (n4 >= Vp) return;
    const float* srow = lmW + (size_t)k * Vv;
    float4 w;
    w.x = (n4 + 0 < Vv) ? tf32r(srow[n4 + 0]) : 0.0f;
    w.y = (n4 + 1 < Vv) ? tf32r(srow[n4 + 1]) : 0.0f;
    w.z = (n4 + 2 < Vv) ? tf32r(srow[n4 + 2]) : 0.0f;
    w.w = (n4 + 3 < Vv) ? tf32r(srow[n4 + 3]) : 0.0f;
    *(float4*)(dst + (size_t)k * Vp + n4) = w;
}

// ============================================================
// Embedding
// ============================================================
__global__ void embed_kernel(const int* __restrict__ idx,
                             const float* __restrict__ tok,
                             float* __restrict__ x) {
    int gid = blockIdx.x * blockDim.x + threadIdx.x;
    if (gid >= BT * Dd) return;
    int row = gid / Dd;
    int d   = gid - row * Dd;
    x[gid] = tok[(size_t)idx[row] * Dd + d];
}

// ============================================================
// Pack Wq/Wk/Wv (L,H,D,HS) -> wpk[L][D][3*H*HS], tf32-rounded
// ============================================================
__global__ void pack_kernel(const float* __restrict__ Wq,
                            const float* __restrict__ Wk,
                            const float* __restrict__ Wv,
                            float* __restrict__ wp) {
    int gid = blockIdx.x * blockDim.x + threadIdx.x;
    const int total = Ll * Hh * Dd * HSs;
    if (gid >= total) return;
    int s = gid & (HSs - 1);
    int d = (gid >> 6) % Dd;
    int h = (gid / (HSs * Dd)) % Hh;
    int l = gid / (HSs * Dd * Hh);
    size_t src = (((size_t)(l * Hh + h) * Dd) + d) * HSs + s;
    size_t dstRow = (size_t)(l * Dd + d) * QKVN;
    int col = h * HSs + s;
    wp[dstRow + col]            = tf32r(Wq[src]);
    wp[dstRow + Dd + col]       = tf32r(Wk[src]);
    wp[dstRow + 2 * Dd + col]   = tf32r(Wv[src]);
}

// ============================================================
// LayerNorm (D=384), 128 threads/row — output tf32-rounded
// ============================================================
__global__ __launch_bounds__(128) void ln_kernel(const float* __restrict__ x,
                                                 const float* __restrict__ g,
                                                 const float* __restrict__ b,
                                                 float* __restrict__ y) {
    int row = blockIdx.x;
    const float* xr = x + (size_t)row * Dd;
    int tid = threadIdx.x;
    float v0 = xr[tid], v1 = xr[tid + 128], v2 = xr[tid + 256];
    float s = v0 + v1 + v2;
    __shared__ float red[4];
    #pragma unroll
    for (int o = 16; o; o >>= 1) s += __shfl_xor_sync(~0u, s, o);
    if ((tid & 31) == 0) red[tid >> 5] = s;
    __syncthreads();
    float mean = (red[0] + red[1] + red[2] + red[3]) * (1.0f / Dd);
    float d0 = v0 - mean, d1 = v1 - mean, d2 = v2 - mean;
    float q = d0 * d0 + d1 * d1 + d2 * d2;
    __syncthreads();
    #pragma unroll
    for (int o = 16; o; o >>= 1) q += __shfl_xor_sync(~0u, q, o);
    if ((tid & 31) == 0) red[tid >> 5] = q;
    __syncthreads();
    float var = (red[0] + red[1] + red[2] + red[3]) * (1.0f / Dd);
    float rstd = rsqrtf(var + 1e-5f);
    float* yr = y + (size_t)row * Dd;
    yr[tid]       = tf32r(d0 * rstd * g[tid]       + b[tid]);
    yr[tid + 128] = tf32r(d1 * rstd * g[tid + 128] + b[tid + 128]);
    yr[tid + 256] = tf32r(d2 * rstd * g[tid + 256] + b[tid + 256]);
}

// ============================================================
// RoPE (exact replica of reference semantics)
// ============================================================
__global__ void rope_kernel(float* __restrict__ qkv) {
    int gid = blockIdx.x * blockDim.x + threadIdx.x;
    const int total = Bb * Tt * Hh * 32;
    if (gid >= total) return;
    int i  = gid & 31;
    int h  = (gid >> 5) % Hh;
    int bt = gid / (32 * Hh);
    int t  = bt & (Tt - 1);
    const float lg = -9.210340371976184f / 64.0f;
    float S, C;
    float tf = (float)t;
    if ((i & 1) == 0) {
        S = sinf(tf * expf(lg * (float)i));
        C = sinf(tf * expf(lg * (float)(32 + i)));
    } else {
        S = cosf(tf * expf(lg * (float)(i - 1)));
        C = cosf(tf * expf(lg * (float)(31 + i)));
    }
    size_t rowq = (size_t)bt * QKVN + h * HSs;
    float qe = qkv[rowq + 2 * i], qo = qkv[rowq + 2 * i + 1];
    qkv[rowq + 2 * i]     = -qo * C;
    qkv[rowq + 2 * i + 1] =  qe * S;
    float* kp = qkv + rowq + Dd;
    float ke = kp[2 * i], ko = kp[2 * i + 1];
    kp[2 * i]     = -ko * C;
    kp[2 * i + 1] =  ke * S;
}

// ============================================================
// Fused causal attention — output tf32-rounded (feeds proj GEMM A)
// ============================================================
__global__ __launch_bounds__(128) void attn_kernel(const float* __restrict__ qkv,
                                                   float* __restrict__ att) {
    __shared__ __align__(16) float Ks[64 * 64];
    __shared__ __align__(16) float Vs[64 * 64];
    int b = blockIdx.x / Hh, h = blockIdx.x % Hh;
    int tid = threadIdx.x;
    int t = blockIdx.y * 128 + tid;
    size_t qrow = ((size_t)(b * Tt + t)) * QKVN + h * HSs;
    float qr[64];
    #pragma unroll
    for (int c = 0; c < 16; ++c) {
        float4 v = *(const float4*)(qkv + qrow + c * 4);
        qr[c*4+0] = v.x; qr[c*4+1] = v.y; qr[c*4+2] = v.z; qr[c*4+3] = v.w;
    }
    const float sc = 0.125f * 1.4426950408889634f;
    #pragma unroll
    for (int d = 0; d < 64; ++d) qr[d] *= sc;

    float mrun = -1e30f, ssum = 0.0f;
    float acc[64];
    #pragma unroll
    for (int d = 0; d < 64; ++d) acc[d] = 0.0f;

    int ntiles = blockIdx.y * 2 + 2;
    for (int tile = 0; tile < ntiles; ++tile) {
        #pragma unroll
        for (int u = 0; u < 8; ++u) {
            int e = tid + u * 128;
            int j = e >> 4;
            int c = (e & 15) << 2;
            size_t src = ((size_t)(b * Tt + tile * 64 + j)) * QKVN + h * HSs + c;
            *(float4*)(Ks + j * 64 + c) = *(const float4*)(qkv + src + Dd);
            *(float4*)(Vs + j * 64 + c) = *(const float4*)(qkv + src + 2 * Dd);
        }
        __syncthreads();
        int jmax = t - tile * 64;
        if (jmax > 63) jmax = 63;
        for (int jj = 0; jj <= jmax; ++jj) {
            const float* kr = Ks + jj * 64;
            float s = 0.0f;
            #pragma unroll
            for (int d = 0; d < 64; ++d) s += qr[d] * kr[d];
            const float* vr = Vs + jj * 64;
            if (s <= mrun) {
                float p = exp2f(s - mrun);
                ssum += p;
                #pragma unroll
                for (int d = 0; d < 64; ++d) acc[d] += p * vr[d];
            } else {
                float corr = exp2f(mrun - s);
                ssum = ssum * corr + 1.0f;
                #pragma unroll
                for (int d = 0; d < 64; ++d) acc[d] = acc[d] * corr + vr[d];
                mrun = s;
            }
        }
        __syncthreads();
    }
    float inv = 1.0f / ssum;
    float* op = att + ((size_t)(b * Tt + t)) * Dd + h * HSs;
    #pragma unroll
    for (int c = 0; c < 16; ++c) {
        float4 v;
        v.x = tf32r(acc[c*4] * inv);   v.y = tf32r(acc[c*4+1] * inv);
        v.z = tf32r(acc[c*4+2] * inv); v.w = tf32r(acc[c*4+3] * inv);
        *(float4*)(op + c * 4) = v;
    }
}

// ============================================================
// Pipelined tf32 tensor-core GEMM, BK=32, STAGES-deep cp.async.
// C(M x Nc) = A(M x K) @ B(K x Nb)[:, :Nc]  [+bias][+res][relu][round]
// Inputs A,B pre-rounded to tf32. Nb % 128 == 0, M % BM == 0, K % 32 == 0.
// BM=64 : 128 thr (4 warps 2x2),  2-stage, minBlocks 3 (12 warps/SM)
// BM=128: 256 thr (8 warps 4x2),  3-stage, minBlocks 2 (16 warps/SM)
// Warptile 32x64.
// ============================================================
template<int BM, int STAGES, bool BIAS, bool RELU, bool RES, bool ROUND>
__global__ void __launch_bounds__(BM == 128 ? 256 : 128, BM == 128 ? 2 : 3)
tgemm_kernel(
    int M, int Nb, int Nc, int K,
    const float* __restrict__ A,
    const float* __restrict__ B,
    const float* __restrict__ bias,
    const float* __restrict__ res,
    float* __restrict__ C) {
    constexpr int BK = 32;
    constexpr int THREADS = (BM == 128) ? 256 : 128;
    constexpr int SA = BK + 4;   // 36
    constexpr int SB = 136;
    extern __shared__ float smem[];
    float* As = smem;                      // [STAGES][BM][SA]
    float* Bs = smem + STAGES * BM * SA;   // [STAGES][BK][SB]

    int tid  = threadIdx.x;
    int warp = tid >> 5, lane = tid & 31;
    int gid  = lane >> 2, tig = lane & 3;
    int m0 = blockIdx.y * BM;
    int n0 = blockIdx.x * 128;
    int warpRow = (warp >> 1) * 32;
    int warpCol = (warp & 1) * 64;

    float c[2][8][4];
    #pragma unroll
    for (int im = 0; im < 2; ++im)
        #pragma unroll
        for (int in = 0; in < 8; ++in)
            #pragma unroll
            for (int r = 0; r < 4; ++r) c[im][in][r] = 0.0f;

    int nk = K / BK;

    auto load_tiles = [&](int kt, int stage) {
        int k0 = kt * BK;
        float* Ash = As + stage * BM * SA;
        float* Bsh = Bs + stage * BK * SB;
        #pragma unroll
        for (int u = 0; u < (BM * 8) / THREADS; ++u) {
            int q  = tid + u * THREADS;
            int r  = q >> 3;
            int c4 = (q & 7) * 4;
            cp_async16(Ash + r * SA + c4, A + (size_t)(m0 + r) * K + k0 + c4);
        }
        #pragma unroll
        for (int u = 0; u < 1024 / THREADS; ++u) {
            int q  = tid + u * THREADS;
            int kk = q >> 5;
            int cc = (q & 31) * 4;
            cp_async16(Bsh + kk * SB + cc, B + (size_t)(k0 + kk) * Nb + n0 + cc);
        }
    };

    #pragma unroll
    for (int s = 0; s < STAGES - 1; ++s) {
        load_tiles(s, s);
        CP_COMMIT();
    }

    int buf = 0;
    for (int kt = 0; kt < nk; ++kt) {
        if (STAGES == 3) {
            if (kt + 2 < nk) { CP_WAIT1(); } else { CP_WAIT0(); }
        } else {
            CP_WAIT0();
        }
        __syncthreads();
        if (kt + STAGES - 1 < nk) {
            int dst = buf + STAGES - 1;
            if (dst >= STAGES) dst -= STAGES;
            load_tiles(kt + STAGES - 1, dst);
            CP_COMMIT();
        }
        const float* Ash = As + buf * BM * SA;
        const float* Bsh = Bs + buf * BK * SB;
        #pragma unroll
        for (int ks = 0; ks < 4; ++ks) {
            int kb = ks * 8;
            uint32_t a[2][4];
            #pragma unroll
            for (int im = 0; im < 2; ++im) {
                int mb = warpRow + im * 16;
                a[im][0] = __float_as_uint(Ash[(mb + gid    ) * SA + kb + tig    ]);
                a[im][1] = __float_as_uint(Ash[(mb + gid + 8) * SA + kb + tig    ]);
                a[im][2] = __float_as_uint(Ash[(mb + gid    ) * SA + kb + tig + 4]);
                a[im][3] = __float_as_uint(Ash[(mb + gid + 8) * SA + kb + tig + 4]);
            }
            #pragma unroll
            for (int in = 0; in < 8; ++in) {
                int nb = warpCol + in * 8 + gid;
                uint32_t b0 = __float_as_uint(Bsh[(kb + tig    ) * SB + nb]);
                uint32_t b1 = __float_as_uint(Bsh[(kb + tig + 4) * SB + nb]);
                mma_tf32(c[0][in], a[0], b0, b1);
                mma_tf32(c[1][in], a[1], b0, b1);
            }
        }
        ++buf;
        if (buf == STAGES) buf = 0;
        __syncthreads();
    }
    // epilogue
    #pragma unroll
    for (int im = 0; im < 2; ++im) {
        int mb = m0 + warpRow + im * 16 + gid;
        #pragma unroll
        for (int in = 0; in < 8; ++in) {
            int n = n0 + warpCol + in * 8 + tig * 2;
            #pragma unroll
            for (int j = 0; j < 2; ++j) {
                int nn = n + j;
                if (nn < Nc) {
                    float bv = BIAS ? bias[nn] : 0.0f;
                    float v0 = c[im][in][j]     + bv;
                    float v1 = c[im][in][j + 2] + bv;
                    int m1 = mb, m2 = mb + 8;
                    if (RES) {
                        v0 += res[(size_t)m1 * Nc + nn];
                        v1 += res[(size_t)m2 * Nc + nn];
                    }
                    if (RELU) { v0 = fmaxf(v0, 0.0f); v1 = fmaxf(v1, 0.0f); }
                    if (ROUND) { v0 = tf32r(v0); v1 = tf32r(v1); }
                    C[(size_t)m1 * Nc + nn] = v0;
                    C[(size_t)m2 * Nc + nn] = v1;
                }
            }
        }
    }
}

// ============================================================
// Host orchestration
// ============================================================
#define SMEM64_2  (2 * ( 64 * 36 + 32 * 136) * 4)   // 53248
#define SMEM128_3 (3 * (128 * 36 + 32 * 136) * 4)   // 107520

extern "C" void kernel_launch(void* const* d_in, const int* in_sizes, int n_in,
                              void* d_out, int out_size) {
    const int*   idx  = (const int*)  d_in[0];
    const float* tok  = (const float*)d_in[1];
    const float* Wq   = (const float*)d_in[2];
    const float* Wk   = (const float*)d_in[3];
    const float* Wv   = (const float*)d_in[4];
    const float* Wp   = (const float*)d_in[5];
    const float* bp   = (const float*)d_in[6];
    const float* W1   = (const float*)d_in[7];
    const float* b1   = (const float*)d_in[8];
    const float* W2   = (const float*)d_in[9];
    const float* b2   = (const float*)d_in[10];
    const float* ln1g = (const float*)d_in[11];
    const float* ln1b = (const float*)d_in[12];
    const float* ln2g = (const float*)d_in[13];
    const float* ln2b = (const float*)d_in[14];
    const float* lnfg = (const float*)d_in[15];
    const float* lnfb = (const float*)d_in[16];
    const float* lmW  = (const float*)d_in[17];
    const float* lmb  = (const float*)d_in[18];
    float* out = (float*)d_out;

    float *px, *pxn, *pqkv, *patt, *ph1, *pwp, *pwpr, *pw1r, *pw2r, *plmp;
    cudaGetSymbolAddress((void**)&px,   g_x);
    cudaGetSymbolAddress((void**)&pxn,  g_xn);
    cudaGetSymbolAddress((void**)&pqkv, g_qkv);
    cudaGetSymbolAddress((void**)&patt, g_att);
    cudaGetSymbolAddress((void**)&ph1,  g_h1);
    cudaGetSymbolAddress((void**)&pwp,  g_wpk);
    cudaGetSymbolAddress((void**)&pwpr, g_wpr);
    cudaGetSymbolAddress((void**)&pw1r, g_w1r);
    cudaGetSymbolAddress((void**)&pw2r, g_w2r);
    cudaGetSymbolAddress((void**)&plmp, g_lmp);

    // raise dynamic-smem limits (idempotent, not an allocation)
    cudaFuncSetAttribute((const void*)tgemm_kernel<64,2,false,false,false,false>,
                         cudaFuncAttributeMaxDynamicSharedMemorySize, SMEM64_2);
    cudaFuncSetAttribute((const void*)tgemm_kernel<64,2,true,false,true,false>,
                         cudaFuncAttributeMaxDynamicSharedMemorySize, SMEM64_2);
    cudaFuncSetAttribute((const void*)tgemm_kernel<64,2,true,true,false,true>,
                         cudaFuncAttributeMaxDynamicSharedMemorySize, SMEM64_2);
    cudaFuncSetAttribute((const void*)tgemm_kernel<128,3,true,false,false,false>,
                         cudaFuncAttributeMaxDynamicSharedMemorySize, SMEM128_3);

    // weight prep (every call; deterministic)
    pack_kernel<<<(Ll*Hh*Dd*HSs + 255) / 256, 256>>>(Wq, Wk, Wv, pwp);
    round_kernel<<<(Ll*Dd*Dd/4 + 255) / 256, 256>>>((const float4*)Wp, (float4*)pwpr, Ll*Dd*Dd/4);
    round_kernel<<<(Ll*Dd*FF/4 + 255) / 256, 256>>>((const float4*)W1, (float4*)pw1r, Ll*Dd*FF/4);
    round_kernel<<<(Ll*FF*Dd/4 + 255) / 256, 256>>>((const float4*)W2, (float4*)pw2r, Ll*FF*Dd/4);
    lmpad_kernel<<<dim3((Vp/4 + 255) / 256, Dd), 256>>>(lmW, plmp);
    embed_kernel<<<(BT*Dd + 255) / 256, 256>>>(idx, tok, px);

    for (int l = 0; l < Ll; ++l) {
        ln_kernel<<<BT, 128>>>(px, ln1g + l * Dd, ln1b + l * Dd, pxn);
        // qkv = xn @ wpk[l]   (2048 x 1152 x 384) — grid 288 CTAs
        tgemm_kernel<64,2,false,false,false,false>
            <<<dim3(QKVN/128, BT/64), 128, SMEM64_2>>>(
            BT, QKVN, QKVN, Dd, pxn, pwp + (size_t)l * Dd * QKVN, nullptr, nullptr, pqkv);
        rope_kernel<<<(Bb*Tt*Hh*32 + 255) / 256, 256>>>(pqkv);
        attn_kernel<<<dim3(Bb * Hh, 2), 128>>>(pqkv, patt);
        // x += att @ Wp[l] + bp[l]   (2048 x 384 x 384)
        tgemm_kernel<64,2,true,false,true,false>
            <<<dim3(Dd/128, BT/64), 128, SMEM64_2>>>(
            BT, Dd, Dd, Dd, patt, pwpr + (size_t)l * Dd * Dd, bp + l * Dd, px, px);
        ln_kernel<<<BT, 128>>>(px, ln2g + l * Dd, ln2b + l * Dd, pxn);
        // h1 = round(relu(xn @ W1 + b1))   (2048 x 1536 x 384) — grid 384 CTAs
        tgemm_kernel<64,2,true,true,false,true>
            <<<dim3(FF/128, BT/64), 128, SMEM64_2>>>(
            BT, FF, FF, Dd, pxn, pw1r + (size_t)l * Dd * FF, b1 + l * FF, nullptr, ph1);
        // x += h1 @ W2 + b2   (2048 x 384 x 1536)
        tgemm_kernel<64,2,true,false,true,false>
            <<<dim3(Dd/128, BT/64), 128, SMEM64_2>>>(
            BT, Dd, Dd, FF, ph1, pw2r + (size_t)l * FF * Dd, b2 + l * Dd, px, px);
    }
    ln_kernel<<<BT, 128>>>(px, lnfg, lnfb, pxn);
    // logits = xn @ lmWpad + lmb   (2048 x 50304(pad)/50257 x 384) — grid 6288 CTAs
    tgemm_kernel<128,3,true,false,false,false>
        <<<dim3(Vp/128, BT/128), 256, SMEM128_3>>>(
        BT, Vp, Vv, Dd, pxn, plmp, lmb, nullptr, out);
}

// round 13
// speedup vs baseline: 1.1239x; 1.1239x over previous
#include <cuda_runtime.h>
#include <cuda_fp16.h>
#include <math.h>
#include <stdint.h>

// Problem constants
#define Vv 50257
#define Vp 50304            // Vv padded to multiple of 128
#define Dd 384
#define Hh 6
#define HSs 64
#define Ll 6
#define Tt 256
#define Bb 8
#define BT (Bb*Tt)          // 2048 rows
#define QKVN (3*Hh*HSs)     // 1152
#define FF (4*Dd)           // 1536

// -------- device scratch (no allocation allowed) --------
__device__ float  g_x   [BT*Dd];          // residual stream (fp32)
__device__ __half g_xn  [BT*Dd];          // LN output (fp16)
__device__ float  g_qkv [BT*QKVN];        // qkv (fp32, rope+attn read it)
__device__ __half g_att [BT*Dd];          // attention output (fp16)
__device__ __half g_h1  [BT*FF];          // mlp hidden (fp16)
__device__ __half g_wpk [Ll*QKVN*Dd];     // packed qkv weights, [l][col][d]
__device__ __half g_wpr [Ll*Dd*Dd];       // Wp transposed [l][n][k]
__device__ __half g_w1r [Ll*FF*Dd];       // W1 transposed [l][n][k]
__device__ __half g_w2r [Ll*Dd*FF];       // W2 transposed [l][n][k]
__device__ __half g_lmp [Vp*Dd];          // lmW transposed+padded [n][k]

// ============================================================
// helpers
// ============================================================
__device__ __forceinline__ void cp_async16(void* dst, const void* src) {
    uint32_t s = (uint32_t)__cvta_generic_to_shared(dst);
    asm volatile("cp.async.cg.shared.global [%0], [%1], 16;\n" :: "r"(s), "l"(src));
}
#define CP_COMMIT() asm volatile("cp.async.commit_group;\n" ::: "memory")
#define CP_WAIT1()  asm volatile("cp.async.wait_group 1;\n" ::: "memory")
#define CP_WAIT0()  asm volatile("cp.async.wait_group 0;\n" ::: "memory")

__device__ __forceinline__ void mma_f16(float* c, const uint32_t* a,
                                        uint32_t b0, uint32_t b1) {
    asm volatile(
        "mma.sync.aligned.m16n8k16.row.col.f32.f16.f16.f32 "
        "{%0,%1,%2,%3}, {%4,%5,%6,%7}, {%8,%9}, {%0,%1,%2,%3};\n"
        : "+f"(c[0]), "+f"(c[1]), "+f"(c[2]), "+f"(c[3])
        : "r"(a[0]), "r"(a[1]), "r"(a[2]), "r"(a[3]), "r"(b0), "r"(b1));
}

// ============================================================
// Weight prep: fp32 [K][N] -> fp16 [Ndst][K] (transposed, padded)
// grid (Ndst/32, K/32, Z); block (32,8). K multiple of 32.
// ============================================================
__global__ void transpose_kernel(const float* __restrict__ src, __half* __restrict__ dst,
                                 int K, int Nsrc, int Ndst) {
    __shared__ float tile[32][33];
    const float* s = src + (size_t)blockIdx.z * K * Nsrc;
    __half* d = dst + (size_t)blockIdx.z * Ndst * K;
    int n0 = blockIdx.x * 32, k0 = blockIdx.y * 32;
    int tx = threadIdx.x, ty = threadIdx.y;
    #pragma unroll
    for (int j = 0; j < 4; ++j) {
        int k = k0 + ty + 8 * j;
        int n = n0 + tx;
        tile[ty + 8 * j][tx] = (n < Nsrc) ? s[(size_t)k * Nsrc + n] : 0.0f;
    }
    __syncthreads();
    #pragma unroll
    for (int j = 0; j < 4; ++j) {
        int n = n0 + ty + 8 * j;
        int k = k0 + tx;
        if (n < Ndst) d[(size_t)n * K + k] = __float2half_rn(tile[tx][ty + 8 * j]);
    }
}

// ============================================================
// Pack Wq/Wk/Wv (L,H,D,HS) fp32 -> wpk [l][col=(w*384+h*64+s)][d] fp16
// grid (Dd/32, Ll*Hh), block 256. Smem-tile transpose per (l,h).
// ============================================================
__global__ void qkvpack_kernel(const float* __restrict__ Wq,
                               const float* __restrict__ Wk,
                               const float* __restrict__ Wv,
                               __half* __restrict__ wp) {
    __shared__ float tile[32][65];
    int d0 = blockIdx.x * 32;
    int lh = blockIdx.y;
    int l = lh / Hh, h = lh % Hh;
    int tid = threadIdx.x;
    const float* srcs[3] = {Wq, Wk, Wv};
    #pragma unroll
    for (int w = 0; w < 3; ++w) {
        const float* S = srcs[w] + (size_t)lh * Dd * HSs;   // [Dd][HSs] block
        for (int i = tid; i < 32 * 64; i += 256) {
            int dd = i >> 6, ss = i & 63;
            tile[dd][ss] = S[(size_t)(d0 + dd) * HSs + ss];
        }
        __syncthreads();
        size_t baseRow = (size_t)l * QKVN + w * 384 + h * 64;
        for (int i = tid; i < 64 * 32; i += 256) {
            int ss = i >> 5, cc = i & 31;
            wp[(baseRow + ss) * Dd + d0 + cc] = __float2half_rn(tile[cc][ss]);
        }
        __syncthreads();
    }
}

// ============================================================
// Embedding (fp32 residual)
// ============================================================
__global__ void embed_kernel(const int* __restrict__ idx,
                             const float* __restrict__ tok,
                             float* __restrict__ x) {
    int gid = blockIdx.x * blockDim.x + threadIdx.x;
    if (gid >= BT * Dd) return;
    int row = gid / Dd;
    int d   = gid - row * Dd;
    x[gid] = tok[(size_t)idx[row] * Dd + d];
}

// ============================================================
// LayerNorm (D=384), 128 threads/row — fp16 output
// ============================================================
__global__ __launch_bounds__(128) void ln_kernel(const float* __restrict__ x,
                                                 const float* __restrict__ g,
                                                 const float* __restrict__ b,
                                                 __half* __restrict__ y) {
    int row = blockIdx.x;
    const float* xr = x + (size_t)row * Dd;
    int tid = threadIdx.x;
    float v0 = xr[tid], v1 = xr[tid + 128], v2 = xr[tid + 256];
    float s = v0 + v1 + v2;
    __shared__ float red[4];
    #pragma unroll
    for (int o = 16; o; o >>= 1) s += __shfl_xor_sync(~0u, s, o);
    if ((tid & 31) == 0) red[tid >> 5] = s;
    __syncthreads();
    float mean = (red[0] + red[1] + red[2] + red[3]) * (1.0f / Dd);
    float d0 = v0 - mean, d1 = v1 - mean, d2 = v2 - mean;
    float q = d0 * d0 + d1 * d1 + d2 * d2;
    __syncthreads();
    #pragma unroll
    for (int o = 16; o; o >>= 1) q += __shfl_xor_sync(~0u, q, o);
    if ((tid & 31) == 0) red[tid >> 5] = q;
    __syncthreads();
    float var = (red[0] + red[1] + red[2] + red[3]) * (1.0f / Dd);
    float rstd = rsqrtf(var + 1e-5f);
    __half* yr = y + (size_t)row * Dd;
    yr[tid]       = __float2half_rn(d0 * rstd * g[tid]       + b[tid]);
    yr[tid + 128] = __float2half_rn(d1 * rstd * g[tid + 128] + b[tid + 128]);
    yr[tid + 256] = __float2half_rn(d2 * rstd * g[tid + 256] + b[tid + 256]);
}

// ============================================================
// RoPE (exact replica of reference semantics), fp32 in-place
// ============================================================
__global__ void rope_kernel(float* __restrict__ qkv) {
    int gid = blockIdx.x * blockDim.x + threadIdx.x;
    const int total = Bb * Tt * Hh * 32;
    if (gid >= total) return;
    int i  = gid & 31;
    int h  = (gid >> 5) % Hh;
    int bt = gid / (32 * Hh);
    int t  = bt & (Tt - 1);
    const float lg = -9.210340371976184f / 64.0f;
    float S, C;
    float tf = (float)t;
    if ((i & 1) == 0) {
        S = sinf(tf * expf(lg * (float)i));
        C = sinf(tf * expf(lg * (float)(32 + i)));
    } else {
        S = cosf(tf * expf(lg * (float)(i - 1)));
        C = cosf(tf * expf(lg * (float)(31 + i)));
    }
    size_t rowq = (size_t)bt * QKVN + h * HSs;
    float qe = qkv[rowq + 2 * i], qo = qkv[rowq + 2 * i + 1];
    qkv[rowq + 2 * i]     = -qo * C;
    qkv[rowq + 2 * i + 1] =  qe * S;
    float* kp = qkv + rowq + Dd;
    float ke = kp[2 * i], ko = kp[2 * i + 1];
    kp[2 * i]     = -ko * C;
    kp[2 * i + 1] =  ke * S;
}

// ============================================================
// Fused causal attention — fp32 compute, fp16 output
// ============================================================
__global__ __launch_bounds__(128) void attn_kernel(const float* __restrict__ qkv,
                                                   __half* __restrict__ att) {
    __shared__ __align__(16) float Ks[64 * 64];
    __shared__ __align__(16) float Vs[64 * 64];
    int b = blockIdx.x / Hh, h = blockIdx.x % Hh;
    int tid = threadIdx.x;
    int t = blockIdx.y * 128 + tid;
    size_t qrow = ((size_t)(b * Tt + t)) * QKVN + h * HSs;
    float qr[64];
    #pragma unroll
    for (int c = 0; c < 16; ++c) {
        float4 v = *(const float4*)(qkv + qrow + c * 4);
        qr[c*4+0] = v.x; qr[c*4+1] = v.y; qr[c*4+2] = v.z; qr[c*4+3] = v.w;
    }
    const float sc = 0.125f * 1.4426950408889634f;
    #pragma unroll
    for (int d = 0; d < 64; ++d) qr[d] *= sc;

    float mrun = -1e30f, ssum = 0.0f;
    float acc[64];
    #pragma unroll
    for (int d = 0; d < 64; ++d) acc[d] = 0.0f;

    int ntiles = blockIdx.y * 2 + 2;
    for (int tile = 0; tile < ntiles; ++tile) {
        #pragma unroll
        for (int u = 0; u < 8; ++u) {
            int e = tid + u * 128;
            int j = e >> 4;
            int c = (e & 15) << 2;
            size_t src = ((size_t)(b * Tt + tile * 64 + j)) * QKVN + h * HSs + c;
            *(float4*)(Ks + j * 64 + c) = *(const float4*)(qkv + src + Dd);
            *(float4*)(Vs + j * 64 + c) = *(const float4*)(qkv + src + 2 * Dd);
        }
        __syncthreads();
        int jmax = t - tile * 64;
        if (jmax > 63) jmax = 63;
        for (int jj = 0; jj <= jmax; ++jj) {
            const float* kr = Ks + jj * 64;
            float s = 0.0f;
            #pragma unroll
            for (int d = 0; d < 64; ++d) s += qr[d] * kr[d];
            const float* vr = Vs + jj * 64;
            if (s <= mrun) {
                float p = exp2f(s - mrun);
                ssum += p;
                #pragma unroll
                for (int d = 0; d < 64; ++d) acc[d] += p * vr[d];
            } else {
                float corr = exp2f(mrun - s);
                ssum = ssum * corr + 1.0f;
                #pragma unroll
                for (int d = 0; d < 64; ++d) acc[d] = acc[d] * corr + vr[d];
                mrun = s;
            }
        }
        __syncthreads();
    }
    float inv = 1.0f / ssum;
    __half2* oph = (__half2*)(att + ((size_t)(b * Tt + t)) * Dd + h * HSs);
    #pragma unroll
    for (int c = 0; c < 16; ++c) {
        oph[c * 2]     = __floats2half2_rn(acc[c*4]     * inv, acc[c*4 + 1] * inv);
        oph[c * 2 + 1] = __floats2half2_rn(acc[c*4 + 2] * inv, acc[c*4 + 3] * inv);
    }
}

// ============================================================
// fp16 tensor-core GEMM (m16n8k16, fp32 accum), 3-stage cp.async.
// C(M x Nc) = A(M x K) @ Bt(Nrows x K)^T  [+bias][+res][relu]
// A: fp16 [M][K]; Bt: fp16 [>=n0+128][K] (pre-transposed weights).
// BM=128: 256 thr (8 warps 4x2). BM=64: 128 thr (4 warps 2x2).
// Warptile 32x64. K % 32 == 0, M % BM == 0.
// ============================================================
template<int BM, bool BIAS, bool RELU, bool RES, bool OUTH>
__global__ void __launch_bounds__(BM == 128 ? 256 : 128)
hgemm_kernel(
    int M, int Nc, int K,
    const __half* __restrict__ A,
    const __half* __restrict__ Bt,
    const float* __restrict__ bias,
    const float* __restrict__ res,
    void* __restrict__ Cout) {
    constexpr int BK = 32;        // halfs per k-tile
    constexpr int THREADS = (BM == 128) ? 256 : 128;
    constexpr int SAh = BK + 8;   // 40 halfs (80B rows -> conflict-free)
    constexpr int STAGES = 3;
    extern __shared__ __half hsm[];
    __half* As = hsm;                          // [ST][BM][SAh]
    __half* Bs = hsm + STAGES * BM * SAh;      // [ST][128][SAh]

    int tid  = threadIdx.x;
    int warp = tid >> 5, lane = tid & 31;
    int gid  = lane >> 2, tig = lane & 3;
    int m0 = blockIdx.y * BM;
    int n0 = blockIdx.x * 128;
    int warpRow = (warp >> 1) * 32;
    int warpCol = (warp & 1) * 64;

    float c[2][8][4];
    #pragma unroll
    for (int im = 0; im < 2; ++im)
        #pragma unroll
        for (int in = 0; in < 8; ++in)
            #pragma unroll
            for (int r = 0; r < 4; ++r) c[im][in][r] = 0.0f;

    int nk = K / BK;

    auto load_tiles = [&](int kt, int stage) {
        int k0 = kt * BK;
        __half* Ash = As + stage * BM * SAh;
        __half* Bsh = Bs + stage * 128 * SAh;
        // A tile: BM rows x 4 chunks of 8 halfs
        #pragma unroll
        for (int u = 0; u < (BM * 4) / THREADS; ++u) {
            int q  = tid + u * THREADS;
            int r  = q >> 2;
            int ch = (q & 3) * 8;
            cp_async16(Ash + r * SAh + ch, A + (size_t)(m0 + r) * K + k0 + ch);
        }
        // B tile: 128 rows x 4 chunks
        #pragma unroll
        for (int u = 0; u < 512 / THREADS; ++u) {
            int q  = tid + u * THREADS;
            int r  = q >> 2;
            int ch = (q & 3) * 8;
            cp_async16(Bsh + r * SAh + ch, Bt + (size_t)(n0 + r) * K + k0 + ch);
        }
    };

    load_tiles(0, 0); CP_COMMIT();
    load_tiles(1, 1); CP_COMMIT();

    int buf = 0;
    for (int kt = 0; kt < nk; ++kt) {
        if (kt + 2 < nk) { CP_WAIT1(); } else { CP_WAIT0(); }
        __syncthreads();
        if (kt + 2 < nk) {
            load_tiles(kt + 2, buf == 0 ? 2 : buf - 1);  // (buf+2)%3
            CP_COMMIT();
        }
        const __half* Ash = As + buf * BM * SAh;
        const __half* Bsh = Bs + buf * 128 * SAh;

        auto ldA = [&](int ks, uint32_t (*a)[4]) {
            int kb = ks * 16;
            #pragma unroll
            for (int im = 0; im < 2; ++im) {
                int mb = warpRow + im * 16;
                a[im][0] = *(const uint32_t*)(Ash + (mb + gid    ) * SAh + kb + 2 * tig);
                a[im][1] = *(const uint32_t*)(Ash + (mb + gid + 8) * SAh + kb + 2 * tig);
                a[im][2] = *(const uint32_t*)(Ash + (mb + gid    ) * SAh + kb + 2 * tig + 8);
                a[im][3] = *(const uint32_t*)(Ash + (mb + gid + 8) * SAh + kb + 2 * tig + 8);
            }
        };
        auto ldB = [&](int ks, uint32_t* bf) {
            int kb = ks * 16;
            #pragma unroll
            for (int in = 0; in < 8; ++in) {
                int n = warpCol + in * 8 + gid;
                bf[in * 2]     = *(const uint32_t*)(Bsh + n * SAh + kb + 2 * tig);
                bf[in * 2 + 1] = *(const uint32_t*)(Bsh + n * SAh + kb + 2 * tig + 8);
            }
        };

        uint32_t af[2][2][4];
        uint32_t bfb[2][16];
        ldA(0, af[0]);
        ldB(0, bfb[0]);
        #pragma unroll
        for (int ks = 0; ks < 2; ++ks) {
            if (ks == 0) { ldA(1, af[1]); ldB(1, bfb[1]); }
            #pragma unroll
            for (int in = 0; in < 8; ++in) {
                mma_f16(c[0][in], af[ks][0], bfb[ks][in * 2], bfb[ks][in * 2 + 1]);
                mma_f16(c[1][in], af[ks][1], bfb[ks][in * 2], bfb[ks][in * 2 + 1]);
            }
        }
        buf = (buf == 2) ? 0 : buf + 1;
    }
    // epilogue
    float*  Cf = (float*)Cout;
    __half* Ch = (__half*)Cout;
    #pragma unroll
    for (int im = 0; im < 2; ++im) {
        int mb = m0 + warpRow + im * 16 + gid;
        #pragma unroll
        for (int in = 0; in < 8; ++in) {
            int n = n0 + warpCol + in * 8 + tig * 2;
            #pragma unroll
            for (int j = 0; j < 2; ++j) {
                int nn = n + j;
                if (nn < Nc) {
                    float bv = BIAS ? bias[nn] : 0.0f;
                    float v0 = c[im][in][j]     + bv;
                    float v1 = c[im][in][j + 2] + bv;
                    int m1 = mb, m2 = mb + 8;
                    if (RES) {
                        v0 += res[(size_t)m1 * Nc + nn];
                        v1 += res[(size_t)m2 * Nc + nn];
                    }
                    if (RELU) { v0 = fmaxf(v0, 0.0f); v1 = fmaxf(v1, 0.0f); }
                    if (OUTH) {
                        Ch[(size_t)m1 * Nc + nn] = __float2half_rn(v0);
                        Ch[(size_t)m2 * Nc + nn] = __float2half_rn(v1);
                    } else {
                        Cf[(size_t)m1 * Nc + nn] = v0;
                        Cf[(size_t)m2 * Nc + nn] = v1;
                    }
                }
            }
        }
    }
}

// ============================================================
// Host orchestration
// ============================================================
#define SMEMH128 (3 * (128 * 40 + 128 * 40) * 2)   // 61440
#define SMEMH64  (3 * ( 64 * 40 + 128 * 40) * 2)   // 46080

extern "C" void kernel_launch(void* const* d_in, const int* in_sizes, int n_in,
                              void* d_out, int out_size) {
    const int*   idx  = (const int*)  d_in[0];
    const float* tok  = (const float*)d_in[1];
    const float* Wq   = (const float*)d_in[2];
    const float* Wk   = (const float*)d_in[3];
    const float* Wv   = (const float*)d_in[4];
    const float* Wp   = (const float*)d_in[5];
    const float* bp   = (const float*)d_in[6];
    const float* W1   = (const float*)d_in[7];
    const float* b1   = (const float*)d_in[8];
    const float* W2   = (const float*)d_in[9];
    const float* b2   = (const float*)d_in[10];
    const float* ln1g = (const float*)d_in[11];
    const float* ln1b = (const float*)d_in[12];
    const float* ln2g = (const float*)d_in[13];
    const float* ln2b = (const float*)d_in[14];
    const float* lnfg = (const float*)d_in[15];
    const float* lnfb = (const float*)d_in[16];
    const float* lmW  = (const float*)d_in[17];
    const float* lmb  = (const float*)d_in[18];
    float* out = (float*)d_out;

    float *px, *pqkv;
    __half *pxn, *patt, *ph1, *pwp, *pwpr, *pw1r, *pw2r, *plmp;
    cudaGetSymbolAddress((void**)&px,   g_x);
    cudaGetSymbolAddress((void**)&pxn,  g_xn);
    cudaGetSymbolAddress((void**)&pqkv, g_qkv);
    cudaGetSymbolAddress((void**)&patt, g_att);
    cudaGetSymbolAddress((void**)&ph1,  g_h1);
    cudaGetSymbolAddress((void**)&pwp,  g_wpk);
    cudaGetSymbolAddress((void**)&pwpr, g_wpr);
    cudaGetSymbolAddress((void**)&pw1r, g_w1r);
    cudaGetSymbolAddress((void**)&pw2r, g_w2r);
    cudaGetSymbolAddress((void**)&plmp, g_lmp);

    // raise dynamic-smem limits (idempotent, not an allocation)
    cudaFuncSetAttribute((const void*)hgemm_kernel<128,false,false,false,false>,
                         cudaFuncAttributeMaxDynamicSharedMemorySize, SMEMH128);
    cudaFuncSetAttribute((const void*)hgemm_kernel<128,true,true,false,true>,
                         cudaFuncAttributeMaxDynamicSharedMemorySize, SMEMH128);
    cudaFuncSetAttribute((const void*)hgemm_kernel<128,true,false,false,false>,
                         cudaFuncAttributeMaxDynamicSharedMemorySize, SMEMH128);
    cudaFuncSetAttribute((const void*)hgemm_kernel<64,true,false,true,false>,
                         cudaFuncAttributeMaxDynamicSharedMemorySize, SMEMH64);

    // ---- weight prep (every call; deterministic) ----
    qkvpack_kernel<<<dim3(Dd/32, Ll*Hh), 256>>>(Wq, Wk, Wv, pwp);
    transpose_kernel<<<dim3(Dd/32, Dd/32, Ll), dim3(32,8)>>>(Wp, pwpr, Dd, Dd, Dd);
    transpose_kernel<<<dim3(FF/32, Dd/32, Ll), dim3(32,8)>>>(W1, pw1r, Dd, FF, FF);
    transpose_kernel<<<dim3(Dd/32, FF/32, Ll), dim3(32,8)>>>(W2, pw2r, FF, Dd, Dd);
    transpose_kernel<<<dim3(Vp/32, Dd/32, 1), dim3(32,8)>>>(lmW, plmp, Dd, Vv, Vp);
    embed_kernel<<<(BT*Dd + 255) / 256, 256>>>(idx, tok, px);

    for (int l = 0; l < Ll; ++l) {
        ln_kernel<<<BT, 128>>>(px, ln1g + l * Dd, ln1b + l * Dd, pxn);
        // qkv = xn @ Wqkv   (2048 x 1152 x 384), fp32 out
        hgemm_kernel<128,false,false,false,false>
            <<<dim3(QKVN/128, BT/128), 256, SMEMH128>>>(
            BT, QKVN, Dd, pxn, pwp + (size_t)l * QKVN * Dd, nullptr, nullptr, pqkv);
        rope_kernel<<<(Bb*Tt*Hh*32 + 255) / 256, 256>>>(pqkv);
        attn_kernel<<<dim3(Bb * Hh, 2), 128>>>(pqkv, patt);
        // x += att @ Wp + bp   (2048 x 384 x 384)
        hgemm_kernel<64,true,false,true,false>
            <<<dim3(Dd/128, BT/64), 128, SMEMH64>>>(
            BT, Dd, Dd, patt, pwpr + (size_t)l * Dd * Dd, bp + l * Dd, px, px);
        ln_kernel<<<BT, 128>>>(px, ln2g + l * Dd, ln2b + l * Dd, pxn);
        // h1 = relu(xn @ W1 + b1)   (2048 x 1536 x 384), fp16 out
        hgemm_kernel<128,true,true,false,true>
            <<<dim3(FF/128, BT/128), 256, SMEMH128>>>(
            BT, FF, Dd, pxn, pw1r + (size_t)l * FF * Dd, b1 + l * FF, nullptr, ph1);
        // x += h1 @ W2 + b2   (2048 x 384 x 1536)
        hgemm_kernel<64,true,false,true,false>
            <<<dim3(Dd/128, BT/64), 128, SMEMH64>>>(
            BT, Dd, FF, ph1, pw2r + (size_t)l * Dd * FF, b2 + l * Dd, px, px);
    }
    ln_kernel<<<BT, 128>>>(px, lnfg, lnfb, pxn);
    // logits = xn @ lmW + lmb   (2048 x 50257 x 384)
    hgemm_kernel<128,true,false,false,false>
        <<<dim3(Vp/128, BT/128), 256, SMEMH128>>>(
        BT, Vv, Dd, pxn, plmp, lmb, nullptr, out);
}

// round 14
// speedup vs baseline: 1.2096x; 1.0762x over previous
#include <cuda_runtime.h>
#include <cuda_fp16.h>
#include <math.h>
#include <stdint.h>

// Problem constants
#define Vv 50257
#define Vp 50304            // Vv padded to multiple of 128
#define Dd 384
#define Hh 6
#define HSs 64
#define Ll 6
#define Tt 256
#define Bb 8
#define BT (Bb*Tt)          // 2048 rows
#define QKVN (3*Hh*HSs)     // 1152
#define FF (4*Dd)           // 1536

// -------- device scratch (no allocation allowed) --------
__device__ float  g_x   [BT*Dd];          // residual stream (fp32)
__device__ __half g_xn  [BT*Dd];          // LN output (fp16)
__device__ float  g_qkv [BT*QKVN];        // qkv (fp32, rope+attn read it)
__device__ __half g_att [BT*Dd];          // attention output (fp16)
__device__ __half g_h1  [BT*FF];          // mlp hidden (fp16)
__device__ __half g_wpk [Ll*QKVN*Dd];     // packed qkv weights, [l][col][d]
__device__ __half g_wpr [Ll*Dd*Dd];       // Wp transposed [l][n][k]
__device__ __half g_w1r [Ll*FF*Dd];       // W1 transposed [l][n][k]
__device__ __half g_w2r [Ll*Dd*FF];       // W2 transposed [l][n][k]
__device__ __half g_lmp [Vp*Dd];          // lmW transposed+padded [n][k]

// ============================================================
// helpers
// ============================================================
__device__ __forceinline__ void cp_async16(void* dst, const void* src) {
    uint32_t s = (uint32_t)__cvta_generic_to_shared(dst);
    asm volatile("cp.async.cg.shared.global [%0], [%1], 16;\n" :: "r"(s), "l"(src));
}
#define CP_COMMIT() asm volatile("cp.async.commit_group;\n" ::: "memory")
#define CP_WAIT1()  asm volatile("cp.async.wait_group 1;\n" ::: "memory")
#define CP_WAIT0()  asm volatile("cp.async.wait_group 0;\n" ::: "memory")

__device__ __forceinline__ void mma_f16(float* c, const uint32_t* a,
                                        uint32_t b0, uint32_t b1) {
    asm volatile(
        "mma.sync.aligned.m16n8k16.row.col.f32.f16.f16.f32 "
        "{%0,%1,%2,%3}, {%4,%5,%6,%7}, {%8,%9}, {%0,%1,%2,%3};\n"
        : "+f"(c[0]), "+f"(c[1]), "+f"(c[2]), "+f"(c[3])
        : "r"(a[0]), "r"(a[1]), "r"(a[2]), "r"(a[3]), "r"(b0), "r"(b1));
}

__device__ __forceinline__ void ldsm_x4(uint32_t& r0, uint32_t& r1,
                                        uint32_t& r2, uint32_t& r3, uint32_t addr) {
    asm volatile("ldmatrix.sync.aligned.m8n8.x4.shared.b16 {%0,%1,%2,%3}, [%4];"
        : "=r"(r0), "=r"(r1), "=r"(r2), "=r"(r3) : "r"(addr));
}

// ============================================================
// Weight prep: fp32 [K][N] -> fp16 [Ndst][K] (transposed, padded)
// ============================================================
__global__ void transpose_kernel(const float* __restrict__ src, __half* __restrict__ dst,
                                 int K, int Nsrc, int Ndst) {
    __shared__ float tile[32][33];
    const float* s = src + (size_t)blockIdx.z * K * Nsrc;
    __half* d = dst + (size_t)blockIdx.z * Ndst * K;
    int n0 = blockIdx.x * 32, k0 = blockIdx.y * 32;
    int tx = threadIdx.x, ty = threadIdx.y;
    #pragma unroll
    for (int j = 0; j < 4; ++j) {
        int k = k0 + ty + 8 * j;
        int n = n0 + tx;
        tile[ty + 8 * j][tx] = (n < Nsrc) ? s[(size_t)k * Nsrc + n] : 0.0f;
    }
    __syncthreads();
    #pragma unroll
    for (int j = 0; j < 4; ++j) {
        int n = n0 + ty + 8 * j;
        int k = k0 + tx;
        if (n < Ndst) d[(size_t)n * K + k] = __float2half_rn(tile[tx][ty + 8 * j]);
    }
}

// ============================================================
// Pack Wq/Wk/Wv (L,H,D,HS) fp32 -> wpk [l][col][d] fp16
// ============================================================
__global__ void qkvpack_kernel(const float* __restrict__ Wq,
                               const float* __restrict__ Wk,
                               const float* __restrict__ Wv,
                               __half* __restrict__ wp) {
    __shared__ float tile[32][65];
    int d0 = blockIdx.x * 32;
    int lh = blockIdx.y;
    int l = lh / Hh, h = lh % Hh;
    int tid = threadIdx.x;
    const float* srcs[3] = {Wq, Wk, Wv};
    #pragma unroll
    for (int w = 0; w < 3; ++w) {
        const float* S = srcs[w] + (size_t)lh * Dd * HSs;
        for (int i = tid; i < 32 * 64; i += 256) {
            int dd = i >> 6, ss = i & 63;
            tile[dd][ss] = S[(size_t)(d0 + dd) * HSs + ss];
        }
        __syncthreads();
        size_t baseRow = (size_t)l * QKVN + w * 384 + h * 64;
        for (int i = tid; i < 64 * 32; i += 256) {
            int ss = i >> 5, cc = i & 31;
            wp[(baseRow + ss) * Dd + d0 + cc] = __float2half_rn(tile[cc][ss]);
        }
        __syncthreads();
    }
}

// ============================================================
// Embedding (fp32 residual)
// ============================================================
__global__ void embed_kernel(const int* __restrict__ idx,
                             const float* __restrict__ tok,
                             float* __restrict__ x) {
    int gid = blockIdx.x * blockDim.x + threadIdx.x;
    if (gid >= BT * Dd) return;
    int row = gid / Dd;
    int d   = gid - row * Dd;
    x[gid] = tok[(size_t)idx[row] * Dd + d];
}

// ============================================================
// LayerNorm (D=384), 128 threads/row — fp16 output
// ============================================================
__global__ __launch_bounds__(128) void ln_kernel(const float* __restrict__ x,
                                                 const float* __restrict__ g,
                                                 const float* __restrict__ b,
                                                 __half* __restrict__ y) {
    int row = blockIdx.x;
    const float* xr = x + (size_t)row * Dd;
    int tid = threadIdx.x;
    float v0 = xr[tid], v1 = xr[tid + 128], v2 = xr[tid + 256];
    float s = v0 + v1 + v2;
    __shared__ float red[4];
    #pragma unroll
    for (int o = 16; o; o >>= 1) s += __shfl_xor_sync(~0u, s, o);
    if ((tid & 31) == 0) red[tid >> 5] = s;
    __syncthreads();
    float mean = (red[0] + red[1] + red[2] + red[3]) * (1.0f / Dd);
    float d0 = v0 - mean, d1 = v1 - mean, d2 = v2 - mean;
    float q = d0 * d0 + d1 * d1 + d2 * d2;
    __syncthreads();
    #pragma unroll
    for (int o = 16; o; o >>= 1) q += __shfl_xor_sync(~0u, q, o);
    if ((tid & 31) == 0) red[tid >> 5] = q;
    __syncthreads();
    float var = (red[0] + red[1] + red[2] + red[3]) * (1.0f / Dd);
    float rstd = rsqrtf(var + 1e-5f);
    __half* yr = y + (size_t)row * Dd;
    yr[tid]       = __float2half_rn(d0 * rstd * g[tid]       + b[tid]);
    yr[tid + 128] = __float2half_rn(d1 * rstd * g[tid + 128] + b[tid + 128]);
    yr[tid + 256] = __float2half_rn(d2 * rstd * g[tid + 256] + b[tid + 256]);
}

// ============================================================
// RoPE (exact replica of reference semantics), fp32 in-place
// ============================================================
__global__ void rope_kernel(float* __restrict__ qkv) {
    int gid = blockIdx.x * blockDim.x + threadIdx.x;
    const int total = Bb * Tt * Hh * 32;
    if (gid >= total) return;
    int i  = gid & 31;
    int h  = (gid >> 5) % Hh;
    int bt = gid / (32 * Hh);
    int t  = bt & (Tt - 1);
    const float lg = -9.210340371976184f / 64.0f;
    float S, C;
    float tf = (float)t;
    if ((i & 1) == 0) {
        S = sinf(tf * expf(lg * (float)i));
        C = sinf(tf * expf(lg * (float)(32 + i)));
    } else {
        S = cosf(tf * expf(lg * (float)(i - 1)));
        C = cosf(tf * expf(lg * (float)(31 + i)));
    }
    size_t rowq = (size_t)bt * QKVN + h * HSs;
    float qe = qkv[rowq + 2 * i], qo = qkv[rowq + 2 * i + 1];
    qkv[rowq + 2 * i]     = -qo * C;
    qkv[rowq + 2 * i + 1] =  qe * S;
    float* kp = qkv + rowq + Dd;
    float ke = kp[2 * i], ko = kp[2 * i + 1];
    kp[2 * i]     = -ko * C;
    kp[2 * i + 1] =  ke * S;
}

// ============================================================
// Fused causal attention — fp32 compute, fp16 output
// ============================================================
__global__ __launch_bounds__(128) void attn_kernel(const float* __restrict__ qkv,
                                                   __half* __restrict__ att) {
    __shared__ __align__(16) float Ks[64 * 64];
    __shared__ __align__(16) float Vs[64 * 64];
    int b = blockIdx.x / Hh, h = blockIdx.x % Hh;
    int tid = threadIdx.x;
    int t = blockIdx.y * 128 + tid;
    size_t qrow = ((size_t)(b * Tt + t)) * QKVN + h * HSs;
    float qr[64];
    #pragma unroll
    for (int c = 0; c < 16; ++c) {
        float4 v = *(const float4*)(qkv + qrow + c * 4);
        qr[c*4+0] = v.x; qr[c*4+1] = v.y; qr[c*4+2] = v.z; qr[c*4+3] = v.w;
    }
    const float sc = 0.125f * 1.4426950408889634f;
    #pragma unroll
    for (int d = 0; d < 64; ++d) qr[d] *= sc;

    float mrun = -1e30f, ssum = 0.0f;
    float acc[64];
    #pragma unroll
    for (int d = 0; d < 64; ++d) acc[d] = 0.0f;

    int ntiles = blockIdx.y * 2 + 2;
    for (int tile = 0; tile < ntiles; ++tile) {
        #pragma unroll
        for (int u = 0; u < 8; ++u) {
            int e = tid + u * 128;
            int j = e >> 4;
            int c = (e & 15) << 2;
            size_t src = ((size_t)(b * Tt + tile * 64 + j)) * QKVN + h * HSs + c;
            *(float4*)(Ks + j * 64 + c) = *(const float4*)(qkv + src + Dd);
            *(float4*)(Vs + j * 64 + c) = *(const float4*)(qkv + src + 2 * Dd);
        }
        __syncthreads();
        int jmax = t - tile * 64;
        if (jmax > 63) jmax = 63;
        for (int jj = 0; jj <= jmax; ++jj) {
            const float* kr = Ks + jj * 64;
            float s = 0.0f;
            #pragma unroll
            for (int d = 0; d < 64; ++d) s += qr[d] * kr[d];
            const float* vr = Vs + jj * 64;
            if (s <= mrun) {
                float p = exp2f(s - mrun);
                ssum += p;
                #pragma unroll
                for (int d = 0; d < 64; ++d) acc[d] += p * vr[d];
            } else {
                float corr = exp2f(mrun - s);
                ssum = ssum * corr + 1.0f;
                #pragma unroll
                for (int d = 0; d < 64; ++d) acc[d] = acc[d] * corr + vr[d];
                mrun = s;
            }
        }
        __syncthreads();
    }
    float inv = 1.0f / ssum;
    __half2* oph = (__half2*)(att + ((size_t)(b * Tt + t)) * Dd + h * HSs);
    #pragma unroll
    for (int c = 0; c < 16; ++c) {
        oph[c * 2]     = __floats2half2_rn(acc[c*4]     * inv, acc[c*4 + 1] * inv);
        oph[c * 2 + 1] = __floats2half2_rn(acc[c*4 + 2] * inv, acc[c*4 + 3] * inv);
    }
}

// ============================================================
// fp16 tensor-core GEMM (m16n8k16, fp32 accum), ldmatrix fragments,
// 3-stage cp.async. C(M x Nc) = A(M x K) @ Bt(rows x K)^T [+bias][+res][relu]
// A: fp16 [M][K]; Bt: fp16 [>=n0+128][K]. BM=128/64. Warptile 32x64.
// ============================================================
template<int BM, bool BIAS, bool RELU, bool RES, bool OUTH>
__global__ void __launch_bounds__(BM == 128 ? 256 : 128)
hgemm_kernel(
    int M, int Nc, int K,
    const __half* __restrict__ A,
    const __half* __restrict__ Bt,
    const float* __restrict__ bias,
    const float* __restrict__ res,
    void* __restrict__ Cout) {
    constexpr int BK = 32;        // halfs per k-tile
    constexpr int THREADS = (BM == 128) ? 256 : 128;
    constexpr int SAh = BK + 8;   // 40 halfs = 80B rows (LDSM conflict-free)
    constexpr int STAGES = 3;
    extern __shared__ __half hsm[];
    __half* As = hsm;                          // [ST][BM][SAh]
    __half* Bs = hsm + STAGES * BM * SAh;      // [ST][128][SAh]
    uint32_t smem_u32 = (uint32_t)__cvta_generic_to_shared(hsm);

    int tid  = threadIdx.x;
    int warp = tid >> 5, lane = tid & 31;
    int gid  = lane >> 2, tig = lane & 3;
    int m0 = blockIdx.y * BM;
    int n0 = blockIdx.x * 128;
    int warpRow = (warp >> 1) * 32;
    int warpCol = (warp & 1) * 64;

    // ldmatrix per-lane offsets (bytes) within a 16x16-half tile region
    uint32_t aoffb = ((uint32_t)(((lane & 7) + ((lane >> 3) & 1) * 8) * SAh
                      + ((lane >> 4) & 1) * 8)) * 2;
    uint32_t boffb = ((uint32_t)(((lane & 7) + ((lane >> 4) & 1) * 8) * SAh
                      + ((lane >> 3) & 1) * 8)) * 2;

    float c[2][8][4];
    #pragma unroll
    for (int im = 0; im < 2; ++im)
        #pragma unroll
        for (int in = 0; in < 8; ++in)
            #pragma unroll
            for (int r = 0; r < 4; ++r) c[im][in][r] = 0.0f;

    int nk = K / BK;

    auto load_tiles = [&](int kt, int stage) {
        int k0 = kt * BK;
        __half* Ash = As + stage * BM * SAh;
        __half* Bsh = Bs + stage * 128 * SAh;
        #pragma unroll
        for (int u = 0; u < (BM * 4) / THREADS; ++u) {
            int q  = tid + u * THREADS;
            int r  = q >> 2;
            int ch = (q & 3) * 8;
            cp_async16(Ash + r * SAh + ch, A + (size_t)(m0 + r) * K + k0 + ch);
        }
        #pragma unroll
        for (int u = 0; u < 512 / THREADS; ++u) {
            int q  = tid + u * THREADS;
            int r  = q >> 2;
            int ch = (q & 3) * 8;
            cp_async16(Bsh + r * SAh + ch, Bt + (size_t)(n0 + r) * K + k0 + ch);
        }
    };

    load_tiles(0, 0); CP_COMMIT();
    load_tiles(1, 1); CP_COMMIT();

    int buf = 0;
    for (int kt = 0; kt < nk; ++kt) {
        if (kt + 2 < nk) { CP_WAIT1(); } else { CP_WAIT0(); }
        __syncthreads();
        if (kt + 2 < nk) {
            load_tiles(kt + 2, buf == 0 ? 2 : buf - 1);
            CP_COMMIT();
        }
        uint32_t AshU = smem_u32 + (uint32_t)(buf * BM * SAh) * 2;
        uint32_t BshU = smem_u32 + (uint32_t)((STAGES * BM + buf * 128) * SAh) * 2;

        #pragma unroll
        for (int ks = 0; ks < 2; ++ks) {
            uint32_t kofs = (uint32_t)(ks * 16) * 2;
            uint32_t a[2][4];
            ldsm_x4(a[0][0], a[0][1], a[0][2], a[0][3],
                    AshU + (uint32_t)(warpRow * SAh) * 2 + kofs + aoffb);
            ldsm_x4(a[1][0], a[1][1], a[1][2], a[1][3],
                    AshU + (uint32_t)((warpRow + 16) * SAh) * 2 + kofs + aoffb);
            uint32_t bfr[16];
            #pragma unroll
            for (int p = 0; p < 4; ++p) {
                ldsm_x4(bfr[p*4], bfr[p*4+1], bfr[p*4+2], bfr[p*4+3],
                        BshU + (uint32_t)((warpCol + p * 16) * SAh) * 2 + kofs + boffb);
            }
            #pragma unroll
            for (int in = 0; in < 8; ++in) {
                int p = in >> 1, hb = in & 1;
                uint32_t b0 = bfr[p * 4 + hb * 2];
                uint32_t b1 = bfr[p * 4 + hb * 2 + 1];
                mma_f16(c[0][in], a[0], b0, b1);
                mma_f16(c[1][in], a[1], b0, b1);
            }
        }
        buf = (buf == 2) ? 0 : buf + 1;
    }
    // epilogue
    float*  Cf = (float*)Cout;
    __half* Ch = (__half*)Cout;
    #pragma unroll
    for (int im = 0; im < 2; ++im) {
        int mb = m0 + warpRow + im * 16 + gid;
        #pragma unroll
        for (int in = 0; in < 8; ++in) {
            int n = n0 + warpCol + in * 8 + tig * 2;
            #pragma unroll
            for (int j = 0; j < 2; ++j) {
                int nn = n + j;
                if (nn < Nc) {
                    float bv = BIAS ? bias[nn] : 0.0f;
                    float v0 = c[im][in][j]     + bv;
                    float v1 = c[im][in][j + 2] + bv;
                    int m1 = mb, m2 = mb + 8;
                    if (RES) {
                        v0 += res[(size_t)m1 * Nc + nn];
                        v1 += res[(size_t)m2 * Nc + nn];
                    }
                    if (RELU) { v0 = fmaxf(v0, 0.0f); v1 = fmaxf(v1, 0.0f); }
                    if (OUTH) {
                        Ch[(size_t)m1 * Nc + nn] = __float2half_rn(v0);
                        Ch[(size_t)m2 * Nc + nn] = __float2half_rn(v1);
                    } else {
                        Cf[(size_t)m1 * Nc + nn] = v0;
                        Cf[(size_t)m2 * Nc + nn] = v1;
                    }
                }
            }
        }
    }
}

// ============================================================
// Host orchestration
// ============================================================
#define SMEMH128 (3 * (128 * 40 + 128 * 40) * 2)   // 61440
#define SMEMH64  (3 * ( 64 * 40 + 128 * 40) * 2)   // 46080

extern "C" void kernel_launch(void* const* d_in, const int* in_sizes, int n_in,
                              void* d_out, int out_size) {
    const int*   idx  = (const int*)  d_in[0];
    const float* tok  = (const float*)d_in[1];
    const float* Wq   = (const float*)d_in[2];
    const float* Wk   = (const float*)d_in[3];
    const float* Wv   = (const float*)d_in[4];
    const float* Wp   = (const float*)d_in[5];
    const float* bp   = (const float*)d_in[6];
    const float* W1   = (const float*)d_in[7];
    const float* b1   = (const float*)d_in[8];
    const float* W2   = (const float*)d_in[9];
    const float* b2   = (const float*)d_in[10];
    const float* ln1g = (const float*)d_in[11];
    const float* ln1b = (const float*)d_in[12];
    const float* ln2g = (const float*)d_in[13];
    const float* ln2b = (const float*)d_in[14];
    const float* lnfg = (const float*)d_in[15];
    const float* lnfb = (const float*)d_in[16];
    const float* lmW  = (const float*)d_in[17];
    const float* lmb  = (const float*)d_in[18];
    float* out = (float*)d_out;

    float *px, *pqkv;
    __half *pxn, *patt, *ph1, *pwp, *pwpr, *pw1r, *pw2r, *plmp;
    cudaGetSymbolAddress((void**)&px,   g_x);
    cudaGetSymbolAddress((void**)&pxn,  g_xn);
    cudaGetSymbolAddress((void**)&pqkv, g_qkv);
    cudaGetSymbolAddress((void**)&patt, g_att);
    cudaGetSymbolAddress((void**)&ph1,  g_h1);
    cudaGetSymbolAddress((void**)&pwp,  g_wpk);
    cudaGetSymbolAddress((void**)&pwpr, g_wpr);
    cudaGetSymbolAddress((void**)&pw1r, g_w1r);
    cudaGetSymbolAddress((void**)&pw2r, g_w2r);
    cudaGetSymbolAddress((void**)&plmp, g_lmp);

    cudaFuncSetAttribute((const void*)hgemm_kernel<128,false,false,false,false>,
                         cudaFuncAttributeMaxDynamicSharedMemorySize, SMEMH128);
    cudaFuncSetAttribute((const void*)hgemm_kernel<128,true,true,false,true>,
                         cudaFuncAttributeMaxDynamicSharedMemorySize, SMEMH128);
    cudaFuncSetAttribute((const void*)hgemm_kernel<128,true,false,false,false>,
                         cudaFuncAttributeMaxDynamicSharedMemorySize, SMEMH128);
    cudaFuncSetAttribute((const void*)hgemm_kernel<64,true,false,true,false>,
                         cudaFuncAttributeMaxDynamicSharedMemorySize, SMEMH64);

    // ---- weight prep (every call; deterministic) ----
    qkvpack_kernel<<<dim3(Dd/32, Ll*Hh), 256>>>(Wq, Wk, Wv, pwp);
    transpose_kernel<<<dim3(Dd/32, Dd/32, Ll), dim3(32,8)>>>(Wp, pwpr, Dd, Dd, Dd);
    transpose_kernel<<<dim3(FF/32, Dd/32, Ll), dim3(32,8)>>>(W1, pw1r, Dd, FF, FF);
    transpose_kernel<<<dim3(Dd/32, FF/32, Ll), dim3(32,8)>>>(W2, pw2r, FF, Dd, Dd);
    transpose_kernel<<<dim3(Vp/32, Dd/32, 1), dim3(32,8)>>>(lmW, plmp, Dd, Vv, Vp);
    embed_kernel<<<(BT*Dd + 255) / 256, 256>>>(idx, tok, px);

    for (int l = 0; l < Ll; ++l) {
        ln_kernel<<<BT, 128>>>(px, ln1g + l * Dd, ln1b + l * Dd, pxn);
        // qkv = xn @ Wqkv   (2048 x 1152 x 384), fp32 out
        hgemm_kernel<128,false,false,false,false>
            <<<dim3(QKVN/128, BT/128), 256, SMEMH128>>>(
            BT, QKVN, Dd, pxn, pwp + (size_t)l * QKVN * Dd, nullptr, nullptr, pqkv);
        rope_kernel<<<(Bb*Tt*Hh*32 + 255) / 256, 256>>>(pqkv);
        attn_kernel<<<dim3(Bb * Hh, 2), 128>>>(pqkv, patt);
        // x += att @ Wp + bp   (2048 x 384 x 384)
        hgemm_kernel<64,true,false,true,false>
            <<<dim3(Dd/128, BT/64), 128, SMEMH64>>>(
            BT, Dd, Dd, patt, pwpr + (size_t)l * Dd * Dd, bp + l * Dd, px, px);
        ln_kernel<<<BT, 128>>>(px, ln2g + l * Dd, ln2b + l * Dd, pxn);
        // h1 = relu(xn @ W1 + b1)   (2048 x 1536 x 384), fp16 out
        hgemm_kernel<128,true,true,false,true>
            <<<dim3(FF/128, BT/128), 256, SMEMH128>>>(
            BT, FF, Dd, pxn, pw1r + (size_t)l * FF * Dd, b1 + l * FF, nullptr, ph1);
        // x += h1 @ W2 + b2   (2048 x 384 x 1536)
        hgemm_kernel<64,true,false,true,false>
            <<<dim3(Dd/128, BT/64), 128, SMEMH64>>>(
            BT, Dd, FF, ph1, pw2r + (size_t)l * Dd * FF, b2 + l * Dd, px, px);
    }
    ln_kernel<<<BT, 128>>>(px, lnfg, lnfb, pxn);
    // logits = xn @ lmW + lmb   (2048 x 50257 x 384)
    hgemm_kernel<128,true,false,false,false>
        <<<dim3(Vp/128, BT/128), 256, SMEMH128>>>(
        BT, Vv, Dd, pxn, plmp, lmb, nullptr, out);
}